// round 1
// baseline (speedup 1.0000x reference)
#include <cuda_runtime.h>
#include <cuda_bf16.h>

#define NMAX 100000
#define EMAX 1000000

// ---------------- scratch (device globals: allocation-free rule) ----------------
__device__ int   g_deg[NMAX];
__device__ int   g_rowptr[NMAX + 1];
__device__ int   g_cursor[NMAX];
__device__ int   g_bsums[128];
__device__ int   g_boff[128];
__device__ float g_invdeg[NMAX];
__device__ int   g_eidx[EMAX];
__device__ float g_mean1[(size_t)NMAX * 64];
__device__ float g_h[(size_t)NMAX * 64];
__device__ float g_hn[(size_t)NMAX * 32];

// ---------------- CSR build ----------------
__global__ void k_zero_deg(int n) {
    int i = blockIdx.x * blockDim.x + threadIdx.x;
    if (i < n) g_deg[i] = 0;
}

__global__ void k_count(const int* __restrict__ dst, int e) {
    int i = blockIdx.x * blockDim.x + threadIdx.x;
    if (i < e) atomicAdd(&g_deg[dst[i]], 1);
}

__global__ void k_scan1(int n) {
    __shared__ int s[1024];
    int tid = threadIdx.x;
    int i = blockIdx.x * 1024 + tid;
    int v = (i < n) ? g_deg[i] : 0;
    s[tid] = v;
    __syncthreads();
#pragma unroll
    for (int off = 1; off < 1024; off <<= 1) {
        int t = (tid >= off) ? s[tid - off] : 0;
        __syncthreads();
        s[tid] += t;
        __syncthreads();
    }
    if (i < n) g_rowptr[i] = s[tid] - v;   // exclusive within block
    if (tid == 1023) g_bsums[blockIdx.x] = s[1023];
}

__global__ void k_scan2(int nb) {
    __shared__ int s[128];
    int tid = threadIdx.x;
    int v = (tid < nb) ? g_bsums[tid] : 0;
    s[tid] = v;
    __syncthreads();
#pragma unroll
    for (int off = 1; off < 128; off <<= 1) {
        int t = (tid >= off) ? s[tid - off] : 0;
        __syncthreads();
        s[tid] += t;
        __syncthreads();
    }
    g_boff[tid] = s[tid] - v;  // exclusive block offsets
}

__global__ void k_scan3(int n, int e) {
    int i = blockIdx.x * 1024 + threadIdx.x;
    if (i < n) {
        int rp = g_rowptr[i] + g_boff[blockIdx.x];
        g_rowptr[i] = rp;
        g_cursor[i] = rp;
        int d = g_deg[i];
        g_invdeg[i] = 1.0f / (float)(d > 1 ? d : 1);
    }
    if (i == 0) g_rowptr[n] = e;
}

__global__ void k_scatter(const int* __restrict__ src, const int* __restrict__ dst, int e) {
    int i = blockIdx.x * blockDim.x + threadIdx.x;
    if (i < e) {
        int d = dst[i];
        int p = atomicAdd(&g_cursor[d], 1);
        g_eidx[p] = src[i];
    }
}

// ---------------- layer-1 aggregation: mean over in-neighbor features (64-d) ----------------
// one warp per node; lane owns one float2 (covers 64 floats)
__global__ void k_agg1(const float* __restrict__ x, int n) {
    int warp = (blockIdx.x * blockDim.x + threadIdx.x) >> 5;
    int lane = threadIdx.x & 31;
    if (warp >= n) return;
    int start = g_rowptr[warp], end = g_rowptr[warp + 1];
    const float2* x2 = (const float2*)x;
    float ax = 0.f, ay = 0.f;
    int e = start;
    for (; e + 4 <= end; e += 4) {
        int s0 = g_eidx[e], s1 = g_eidx[e + 1], s2 = g_eidx[e + 2], s3 = g_eidx[e + 3];
        float2 a = x2[(size_t)s0 * 32 + lane];
        float2 b = x2[(size_t)s1 * 32 + lane];
        float2 c = x2[(size_t)s2 * 32 + lane];
        float2 d = x2[(size_t)s3 * 32 + lane];
        ax += (a.x + b.x) + (c.x + d.x);
        ay += (a.y + b.y) + (c.y + d.y);
    }
    for (; e < end; e++) {
        int s = g_eidx[e];
        float2 a = x2[(size_t)s * 32 + lane];
        ax += a.x; ay += a.y;
    }
    float id = g_invdeg[warp];
    float2 o; o.x = ax * id; o.y = ay * id;
    ((float2*)g_mean1)[(size_t)warp * 32 + lane] = o;
}

// ---------------- layer-1 fused GEMM: h = relu(x@Ws1 + mean1@Wn1 + b1) ----------------
// block = 256 thr (8 warps), 32 nodes/block; warp = 4 nodes, lane = cols {2l, 2l+1}
__global__ void __launch_bounds__(256) k_gemm1(
    const float* __restrict__ x, const float* __restrict__ Wself,
    const float* __restrict__ Wneigh, const float* __restrict__ bias, int n)
{
    __shared__ float Ws[64 * 64];
    __shared__ float Wn[64 * 64];
    __shared__ float xs[32 * 64];
    __shared__ float ms[32 * 64];
    int tid = threadIdx.x;

    for (int i = tid; i < 1024; i += 256) {
        ((float4*)Ws)[i] = ((const float4*)Wself)[i];
        ((float4*)Wn)[i] = ((const float4*)Wneigh)[i];
    }
    int n0 = blockIdx.x * 32;
    for (int i = tid; i < 512; i += 256) {
        int node = n0 + (i >> 4);
        float4 xv = make_float4(0.f, 0.f, 0.f, 0.f), mv = xv;
        if (node < n) {
            xv = ((const float4*)x)[(size_t)node * 16 + (i & 15)];
            mv = ((const float4*)g_mean1)[(size_t)node * 16 + (i & 15)];
        }
        ((float4*)xs)[i] = xv;
        ((float4*)ms)[i] = mv;
    }
    __syncthreads();

    int w = tid >> 5, l = tid & 31;
    int nl = w * 4;
    float acc[4][2];
#pragma unroll
    for (int i = 0; i < 4; i++) { acc[i][0] = 0.f; acc[i][1] = 0.f; }

#pragma unroll 4
    for (int jg = 0; jg < 16; jg++) {
        float xr[4][4], mr[4][4];
#pragma unroll
        for (int i = 0; i < 4; i++) {
            float4 t = *(const float4*)&xs[(nl + i) * 64 + jg * 4];
            xr[i][0] = t.x; xr[i][1] = t.y; xr[i][2] = t.z; xr[i][3] = t.w;
            float4 u = *(const float4*)&ms[(nl + i) * 64 + jg * 4];
            mr[i][0] = u.x; mr[i][1] = u.y; mr[i][2] = u.z; mr[i][3] = u.w;
        }
#pragma unroll
        for (int jj = 0; jj < 4; jj++) {
            int j = jg * 4 + jj;
            float2 ws = *(const float2*)&Ws[j * 64 + 2 * l];
            float2 wn = *(const float2*)&Wn[j * 64 + 2 * l];
#pragma unroll
            for (int i = 0; i < 4; i++) {
                acc[i][0] = fmaf(xr[i][jj], ws.x, fmaf(mr[i][jj], wn.x, acc[i][0]));
                acc[i][1] = fmaf(xr[i][jj], ws.y, fmaf(mr[i][jj], wn.y, acc[i][1]));
            }
        }
    }
    float b0 = __ldg(&bias[2 * l]);
    float b1 = __ldg(&bias[2 * l + 1]);
#pragma unroll
    for (int i = 0; i < 4; i++) {
        int node = n0 + nl + i;
        if (node < n) {
            float2 o;
            o.x = fmaxf(acc[i][0] + b0, 0.f);
            o.y = fmaxf(acc[i][1] + b1, 0.f);
            ((float2*)g_h)[(size_t)node * 32 + l] = o;
        }
    }
}

// ---------------- layer-2 linear: d_out = h@Ws2 + b2 ; g_hn = h@Wn2 ----------------
// block = 256 thr, 32 nodes/block; warp = 4 nodes, lane = col l (32 cols)
__global__ void __launch_bounds__(256) k_lin2(
    const float* __restrict__ Wself, const float* __restrict__ Wneigh,
    const float* __restrict__ bias, float* __restrict__ out, int n)
{
    __shared__ float Ws[64 * 32];
    __shared__ float Wn[64 * 32];
    __shared__ float hs[32 * 64];
    int tid = threadIdx.x;

    for (int i = tid; i < 512; i += 256) {
        ((float4*)Ws)[i] = ((const float4*)Wself)[i];
        ((float4*)Wn)[i] = ((const float4*)Wneigh)[i];
    }
    int n0 = blockIdx.x * 32;
    for (int i = tid; i < 512; i += 256) {
        int node = n0 + (i >> 4);
        float4 hv = make_float4(0.f, 0.f, 0.f, 0.f);
        if (node < n) hv = ((const float4*)g_h)[(size_t)node * 16 + (i & 15)];
        ((float4*)hs)[i] = hv;
    }
    __syncthreads();

    int w = tid >> 5, l = tid & 31;
    int nl = w * 4;
    float accs[4], accn[4];
#pragma unroll
    for (int i = 0; i < 4; i++) { accs[i] = 0.f; accn[i] = 0.f; }

#pragma unroll 4
    for (int jg = 0; jg < 16; jg++) {
        float hr[4][4];
#pragma unroll
        for (int i = 0; i < 4; i++) {
            float4 t = *(const float4*)&hs[(nl + i) * 64 + jg * 4];
            hr[i][0] = t.x; hr[i][1] = t.y; hr[i][2] = t.z; hr[i][3] = t.w;
        }
#pragma unroll
        for (int jj = 0; jj < 4; jj++) {
            int j = jg * 4 + jj;
            float ws = Ws[j * 32 + l];
            float wn = Wn[j * 32 + l];
#pragma unroll
            for (int i = 0; i < 4; i++) {
                accs[i] = fmaf(hr[i][jj], ws, accs[i]);
                accn[i] = fmaf(hr[i][jj], wn, accn[i]);
            }
        }
    }
    float b = __ldg(&bias[l]);
#pragma unroll
    for (int i = 0; i < 4; i++) {
        int node = n0 + nl + i;
        if (node < n) {
            out[(size_t)node * 32 + l] = accs[i] + b;
            g_hn[(size_t)node * 32 + l] = accn[i];
        }
    }
}

// ---------------- layer-2 aggregation: d_out += invdeg * sum(hn[src]) (32-d) ----------------
__global__ void k_agg2(float* __restrict__ out, int n) {
    int warp = (blockIdx.x * blockDim.x + threadIdx.x) >> 5;
    int lane = threadIdx.x & 31;
    if (warp >= n) return;
    int start = g_rowptr[warp], end = g_rowptr[warp + 1];
    float acc = 0.f;
    int e = start;
    for (; e + 4 <= end; e += 4) {
        int s0 = g_eidx[e], s1 = g_eidx[e + 1], s2 = g_eidx[e + 2], s3 = g_eidx[e + 3];
        float a = g_hn[(size_t)s0 * 32 + lane];
        float b = g_hn[(size_t)s1 * 32 + lane];
        float c = g_hn[(size_t)s2 * 32 + lane];
        float d = g_hn[(size_t)s3 * 32 + lane];
        acc += (a + b) + (c + d);
    }
    for (; e < end; e++) {
        int s = g_eidx[e];
        acc += g_hn[(size_t)s * 32 + lane];
    }
    out[(size_t)warp * 32 + lane] += acc * g_invdeg[warp];
}

// ---------------- launcher ----------------
extern "C" void kernel_launch(void* const* d_in, const int* in_sizes, int n_in,
                              void* d_out, int out_size) {
    const float* x   = (const float*)d_in[0];
    const int*   src = (const int*)d_in[1];
    const int*   dst = (const int*)d_in[2];
    const float* ws1 = (const float*)d_in[3];
    const float* wn1 = (const float*)d_in[4];
    const float* b1  = (const float*)d_in[5];
    const float* ws2 = (const float*)d_in[6];
    const float* wn2 = (const float*)d_in[7];
    const float* b2  = (const float*)d_in[8];
    float* out = (float*)d_out;

    int N = in_sizes[0] / 64;
    int E = in_sizes[1];
    int nb1 = (N + 1023) / 1024;

    // CSR build
    k_zero_deg<<<(N + 255) / 256, 256>>>(N);
    k_count<<<(E + 255) / 256, 256>>>(dst, E);
    k_scan1<<<nb1, 1024>>>(N);
    k_scan2<<<1, 128>>>(nb1);
    k_scan3<<<nb1, 1024>>>(N, E);
    k_scatter<<<(E + 255) / 256, 256>>>(src, dst, E);

    // layer 1
    k_agg1<<<(N + 7) / 8, 256>>>(x, N);
    k_gemm1<<<(N + 31) / 32, 256>>>(x, ws1, wn1, b1, N);

    // layer 2
    k_lin2<<<(N + 31) / 32, 256>>>(ws2, wn2, b2, out, N);
    k_agg2<<<(N + 7) / 8, 256>>>(out, N);
}